// round 5
// baseline (speedup 1.0000x reference)
#include <cuda_runtime.h>
#include <cuda_bf16.h>

#define BB 16
#define CC 512
#define MM 256
#define HWN 4096
#define ATTN 32

// ---------------- scratch ----------------
__device__ float g_Y[BB*CC];
__device__ float g_S[BB];
__device__ float g_Gmax[BB*MM];
__device__ float g_ctx[BB*MM];
__device__ float g_up[BB*CC];
__device__ float g_v[BB*CC];
__device__ float g_c0[BB];
__device__ float g_P[BB*CC];
__device__ float g_Q[BB*CC];
__device__ float g_E[BB*HWN];     // exp(spatial ctx)
__device__ float g_Esum[BB];

__device__ __forceinline__ void atomicMaxF(float* addr, float v) {
    int old = __float_as_int(*addr);
    while (__int_as_float(old) < v) {
        int prev = atomicCAS((int*)addr, old, __float_as_int(v));
        if (prev == old) break;
        old = prev;
    }
}

__device__ __forceinline__ float blockSum256(float v, float* red) {
    int t = threadIdx.x, lane = t & 31, warp = t >> 5;
    __syncthreads();
#pragma unroll
    for (int o = 16; o; o >>= 1) v += __shfl_xor_sync(~0u, v, o);
    if (lane == 0) red[warp] = v;
    __syncthreads();
    if (warp == 0) {
        float s = (lane < 8) ? red[lane] : 0.f;
#pragma unroll
        for (int o = 4; o; o >>= 1) s += __shfl_xor_sync(~0u, s, o);
        if (lane == 0) red[0] = s;
    }
    __syncthreads();
    return red[0];
}
__device__ __forceinline__ float blockMax256(float v, float* red) {
    int t = threadIdx.x, lane = t & 31, warp = t >> 5;
    __syncthreads();
#pragma unroll
    for (int o = 16; o; o >>= 1) v = fmaxf(v, __shfl_xor_sync(~0u, v, o));
    if (lane == 0) red[warp] = v;
    __syncthreads();
    if (warp == 0) {
        float s = (lane < 8) ? red[lane] : __int_as_float(0xff800000u);
#pragma unroll
        for (int o = 4; o; o >>= 1) s = fmaxf(s, __shfl_xor_sync(~0u, s, o));
        if (lane == 0) red[0] = s;
    }
    __syncthreads();
    return red[0];
}

// ---------------- K0: init ----------------
__global__ void k0_init() {
    int i = blockIdx.x * 256 + threadIdx.x;
    if (i < BB*CC) g_Y[i] = 0.f;
    if (i < BB*MM) g_Gmax[i] = __int_as_float(0xff800000u);
    if (i < BB) { g_S[i] = 0.f; g_Esum[i] = 0.f; }
}

// ---------------- K12: bf16 GEMM (Gmax) + mask logits + Y accumulation (L2) ----------------
// grid BB*64: (b, mt in {0,1}, nt in 0..31). CTA tile 128(M) x 128(N), K=512.
// mt==0 CTAs additionally finish logits, exp, and do the Y pass over their
// 128-pixel chunk (x chunk is L2-resident after the GEMM mainloop).
__global__ __launch_bounds__(256, 2) void k12(const float* __restrict__ x,
                                              const float* __restrict__ w_qr,
                                              const float* __restrict__ b_qr,
                                              const float* __restrict__ w_ql) {
    __shared__ __nv_bfloat16 As[128][40];
    __shared__ __nv_bfloat16 Bs[128][40];
    __shared__ float sw[CC];      // w_qr
    __shared__ float sl[128];     // logit partials
    __shared__ float se[128];     // exp(logit)
    int bid = blockIdx.x, t = threadIdx.x;
    int b = bid >> 6, r6 = bid & 63;
    int mt = r6 >> 5, nt = r6 & 31;
    int warp = t >> 5, lane = t & 31;
    int wm = warp >> 2, wn = warp & 3;            // 2 x 4 warps; warp tile 64x32
    int n0 = nt * 128;
    const float* xb = x + (size_t)b * CC * HWN + n0;
    const float* wq = w_ql + (size_t)mt * 128 * CC;

    for (int i = t; i < CC; i += 256) sw[i] = w_qr[i];

    float acc[4][4][4];
#pragma unroll
    for (int i = 0; i < 4; i++)
#pragma unroll
        for (int j = 0; j < 4; j++)
#pragma unroll
            for (int k = 0; k < 4; k++) acc[i][j][k] = 0.f;

    float lacc = 0.f;                              // partial mask logit for pixel t&127
    for (int k0 = 0; k0 < CC; k0 += 32) {
        __syncthreads();
#pragma unroll
        for (int p = 0; p < 16; p++) {             // A: 128x32
            int i = t + p * 256;
            int m = i >> 5, k = i & 31;
            As[m][k] = __float2bfloat16(wq[m * CC + k0 + k]);
        }
#pragma unroll
        for (int p = 0; p < 16; p++) {             // B: 32x128 -> Bs[n][k]; fold logit dot
            int i = t + p * 256;
            int n = i & 127, k = i >> 7;
            float val = xb[(size_t)(k0 + k) * HWN + n];
            Bs[n][k] = __float2bfloat16(val);
            lacc += sw[k0 + k] * val;
        }
        __syncthreads();
#pragma unroll
        for (int kb = 0; kb < 32; kb += 16) {
            unsigned af[4][4], bf[4][2];
            int cq = kb + (lane & 3) * 2;
#pragma unroll
            for (int mf = 0; mf < 4; mf++) {
                int r = wm * 64 + mf * 16 + (lane >> 2);
                af[mf][0] = *(const unsigned*)&As[r][cq];
                af[mf][1] = *(const unsigned*)&As[r + 8][cq];
                af[mf][2] = *(const unsigned*)&As[r][cq + 8];
                af[mf][3] = *(const unsigned*)&As[r + 8][cq + 8];
            }
#pragma unroll
            for (int nf = 0; nf < 4; nf++) {
                int n = wn * 32 + nf * 8 + (lane >> 2);
                bf[nf][0] = *(const unsigned*)&Bs[n][cq];
                bf[nf][1] = *(const unsigned*)&Bs[n][cq + 8];
            }
#pragma unroll
            for (int mf = 0; mf < 4; mf++)
#pragma unroll
                for (int nf = 0; nf < 4; nf++)
                    asm volatile(
                        "mma.sync.aligned.m16n8k16.row.col.f32.bf16.bf16.f32 "
                        "{%0,%1,%2,%3}, {%4,%5,%6,%7}, {%8,%9}, {%0,%1,%2,%3};\n"
                        : "+f"(acc[mf][nf][0]), "+f"(acc[mf][nf][1]),
                          "+f"(acc[mf][nf][2]), "+f"(acc[mf][nf][3])
                        : "r"(af[mf][0]), "r"(af[mf][1]), "r"(af[mf][2]), "r"(af[mf][3]),
                          "r"(bf[nf][0]), "r"(bf[nf][1]));
        }
    }

    // row-max -> global Gmax (both mt roles)
#pragma unroll
    for (int mf = 0; mf < 4; mf++) {
        float m0 = __int_as_float(0xff800000u), m1 = m0;
#pragma unroll
        for (int nf = 0; nf < 4; nf++) {
            m0 = fmaxf(m0, fmaxf(acc[mf][nf][0], acc[mf][nf][1]));
            m1 = fmaxf(m1, fmaxf(acc[mf][nf][2], acc[mf][nf][3]));
        }
        m0 = fmaxf(m0, __shfl_xor_sync(~0u, m0, 1));
        m0 = fmaxf(m0, __shfl_xor_sync(~0u, m0, 2));
        m1 = fmaxf(m1, __shfl_xor_sync(~0u, m1, 1));
        m1 = fmaxf(m1, __shfl_xor_sync(~0u, m1, 2));
        if ((lane & 3) == 0) {
            int r = mt * 128 + wm * 64 + mf * 16 + (lane >> 2);
            atomicMaxF(&g_Gmax[b * MM + r], m0);
            atomicMaxF(&g_Gmax[b * MM + r + 8], m1);
        }
    }

    // mt==0: finish logits, exp, S, and Y accumulation over the (L2-hot) chunk
    if (mt == 0) {
        if (t < 128) sl[t] = lacc;
        __syncthreads();
        if (t >= 128) sl[t - 128] += lacc;
        __syncthreads();
        if (t < 128) {
            float e = expf(sl[t] + b_qr[0]);
            se[t] = e;
            float s = e;
#pragma unroll
            for (int o = 16; o; o >>= 1) s += __shfl_xor_sync(~0u, s, o);
            if (lane == 0) atomicAdd(&g_S[b], s);
        }
        __syncthreads();
        const float4* se4 = (const float4*)se;
        for (int cc = t; cc < CC; cc += 256) {
            const float4* xr = (const float4*)(xb + (size_t)cc * HWN);
            float y0 = 0.f, y1 = 0.f;
#pragma unroll 8
            for (int j = 0; j < 32; j += 2) {
                float4 xv = xr[j];     float4 ev = se4[j];
                y0 += ev.x*xv.x + ev.y*xv.y + ev.z*xv.z + ev.w*xv.w;
                float4 xw = xr[j + 1]; float4 ew = se4[j + 1];
                y1 += ew.x*xw.x + ew.y*xw.y + ew.z*xw.z + ew.w*xw.w;
            }
            atomicAdd(&g_Y[b*CC + cc], y0 + y1);
        }
    }
}

// ---------------- K3v: avg = softmax(Gmax+b_ql); v = W_vl^T avg; c0.  grid B ----------------
__global__ void k3v(const float* __restrict__ b_ql,
                    const float* __restrict__ w_vl, const float* __restrict__ b_vl) {
    __shared__ float savg[MM];
    __shared__ float red[8];
    int b = blockIdx.x, t = threadIdx.x;
    float gv = g_Gmax[b*MM + t] + b_ql[t];
    float gm = blockMax256(gv, red);
    float ge = expf(gv - gm);
    float gs = blockSum256(ge, red);
    savg[t] = ge / gs;
    float c0 = blockSum256((ge / gs) * b_vl[t], red);
    if (t == 0) g_c0[b] = c0;
    __syncthreads();
    float a0 = 0.f, a1 = 0.f;
#pragma unroll 8
    for (int m = 0; m < MM; m++) {
        float av = savg[m];
        const float* wr = w_vl + (size_t)m * CC;
        a0 += av * wr[t];
        a1 += av * wr[t + 256];
    }
    g_v[b*CC + t]       = a0;
    g_v[b*CC + t + 256] = a1;
}

// ---------------- K3a: context = W_vr @ (Y/S) + b_vr.  grid (B, 8) ----------------
__global__ void k3a(const float* __restrict__ w_vr, const float* __restrict__ b_vr) {
    __shared__ float sy[CC];
    int b = blockIdx.x, blk = blockIdx.y, t = threadIdx.x;
    int warp = t >> 5, lane = t & 31;
    float Sinv = 1.f / g_S[b];
    for (int i = t; i < CC; i += 256) sy[i] = g_Y[b*CC + i] * Sinv;
    __syncthreads();
#pragma unroll
    for (int i = 0; i < 4; i++) {
        int r = blk * 32 + warp * 4 + i;
        const float* wr = w_vr + (size_t)r * CC;
        float a = 0.f;
#pragma unroll
        for (int c = lane; c < CC; c += 32) a += wr[c] * sy[c];
#pragma unroll
        for (int o = 16; o; o >>= 1) a += __shfl_xor_sync(~0u, a, o);
        if (lane == 0) g_ctx[b*MM + r] = a + b_vr[r];
    }
}

// ---------------- K3b: up = W_up @ ctx + b_up.  grid (B, 16) ----------------
__global__ void k3b(const float* __restrict__ w_up, const float* __restrict__ b_up) {
    __shared__ float sc[MM];
    int b = blockIdx.x, blk = blockIdx.y, t = threadIdx.x;
    int warp = t >> 5, lane = t & 31;
    if (t < MM) sc[t] = g_ctx[b*MM + t];
    __syncthreads();
#pragma unroll
    for (int i = 0; i < 4; i++) {
        int r = blk * 32 + warp * 4 + i;
        const float* wr = w_up + (size_t)r * MM;
        float a = 0.f;
#pragma unroll
        for (int m = lane; m < MM; m += 32) a += wr[m] * sc[m];
#pragma unroll
        for (int o = 16; o; o >>= 1) a += __shfl_xor_sync(~0u, a, o);
        if (lane == 0) g_up[b*CC + r] = a + b_up[r];
    }
}

// ---------------- K3c: LN + sigmoid + SK-attn -> P,Q.  grid B ----------------
__global__ void k3c(const float* __restrict__ ln_g, const float* __restrict__ ln_b,
                    const float* __restrict__ w_red, const float* __restrict__ bn_g,
                    const float* __restrict__ bn_b, const float* __restrict__ bn_rm,
                    const float* __restrict__ bn_rv, const float* __restrict__ w_sel) {
    __shared__ float sy[CC];
    __shared__ float sca[CC];
    __shared__ float ssk[ATTN];
    __shared__ float red[8];
    int b = blockIdx.x, t = threadIdx.x;
    int warp = t >> 5, lane = t & 31;

    float u0 = g_up[b*CC + t], u1 = g_up[b*CC + t + 256];
    float mean = blockSum256(u0 + u1, red) * (1.f / CC);
    float var  = blockSum256(u0*u0 + u1*u1, red) * (1.f / CC) - mean * mean;
    float rstd = rsqrtf(var + 1e-5f);
    sca[t]       = 1.f / (1.f + expf(-((u0 - mean) * rstd * ln_g[t] + ln_b[t])));
    sca[t + 256] = 1.f / (1.f + expf(-((u1 - mean) * rstd * ln_g[t + 256] + ln_b[t + 256])));

    const float invHW = 1.f / (float)HWN;
    sy[t]       = sca[t]       * (1.f + invHW) + invHW;
    sy[t + 256] = sca[t + 256] * (1.f + invHW) + invHW;
    __syncthreads();

#pragma unroll
    for (int i = 0; i < 4; i++) {
        int r = warp * 4 + i;
        const float* wr = w_red + (size_t)r * CC;
        float a = 0.f;
#pragma unroll
        for (int c = lane; c < CC; c += 32) a += wr[c] * sy[c];
#pragma unroll
        for (int o = 16; o; o >>= 1) a += __shfl_xor_sync(~0u, a, o);
        if (lane == 0) {
            a = (a - bn_rm[r]) * rsqrtf(bn_rv[r] + 1e-5f) * bn_g[r] + bn_b[r];
            ssk[r] = fmaxf(a, 0.f);
        }
    }
    __syncthreads();

#pragma unroll
    for (int i = 0; i < 2; i++) {
        int c = t + i * 256;
        float s0 = 0.f, s1 = 0.f;
        const float* w0 = w_sel + (size_t)c * ATTN;
        const float* w1 = w_sel + (size_t)(CC + c) * ATTN;
#pragma unroll
        for (int a = 0; a < ATTN; a++) { s0 += w0[a] * ssk[a]; s1 += w1[a] * ssk[a]; }
        float mx = fmaxf(s0, s1);
        float e0 = expf(s0 - mx), e1 = expf(s1 - mx);
        float inv = 1.f / (e0 + e1);
        float a0 = e0 * inv, a1 = e1 * inv;
        float ca = sca[c];
        g_P[b*CC + c] = a0 * ca + a1;
        g_Q[b*CC + c] = a1 * ca;
    }
}

// ---------------- K4: ctx per pixel = v.x + c0; exp & sum.  512 threads ----------------
// grid (B, 16); thread t: pixel = chunk*256 + (t&255), channel half = t>>8.
__global__ __launch_bounds__(512) void k4_ctx(const float* __restrict__ x) {
    __shared__ float sv[CC];
    __shared__ float part[512];
    __shared__ float red[8];
    int b = blockIdx.x, chunk = blockIdx.y, t = threadIdx.x;
    for (int i = t; i < CC; i += 512) sv[i] = g_v[b*CC + i];
    __syncthreads();
    int hp = t & 255;
    int h = chunk * 256 + hp;
    int ch0 = (t >> 8) * 256;
    const float* xp = x + (size_t)b * CC * HWN + (size_t)ch0 * HWN + h;
    float a0 = 0.f, a1 = 0.f, a2 = 0.f, a3 = 0.f;
#pragma unroll 4
    for (int c = 0; c < 256; c += 4) {
        a0 += sv[ch0 + c]     * xp[(size_t)c * HWN];
        a1 += sv[ch0 + c + 1] * xp[(size_t)(c + 1) * HWN];
        a2 += sv[ch0 + c + 2] * xp[(size_t)(c + 2) * HWN];
        a3 += sv[ch0 + c + 3] * xp[(size_t)(c + 3) * HWN];
    }
    part[t] = (a0 + a1) + (a2 + a3);
    __syncthreads();
    if (t < 256) {
        int lane = t & 31, warp = t >> 5;
        float e = expf(g_c0[b] + part[t] + part[t + 256]);
        g_E[b*HWN + h] = e;
        float s = e;
#pragma unroll
        for (int o = 16; o; o >>= 1) s += __shfl_xor_sync(~0u, s, o);
        if (lane == 0) red[warp] = s;
    }
    __syncthreads();
    if (t == 0) {
        float s = 0.f;
#pragma unroll
        for (int i = 0; i < 8; i++) s += red[i];
        atomicAdd(&g_Esum[b], s);
    }
}

// ---------------- K5: out = x * (1 + Q + P * spatial_attn) ----------------
__global__ void k5_final(const float* __restrict__ x, float* __restrict__ out) {
    int i4 = blockIdx.x * 256 + threadIdx.x;
    int h4 = i4 & 1023;
    int c  = (i4 >> 10) & 511;
    int b  = i4 >> 19;
    float4 xv = ((const float4*)x)[i4];
    float4 ev = ((const float4*)g_E)[b * (HWN/4) + h4];
    float inv = 1.f / g_Esum[b];
    float P = g_P[b*CC + c], Q = g_Q[b*CC + c];
    float base = 1.f + Q;
    float4 o;
    o.x = xv.x * (base + P * ev.x * inv);
    o.y = xv.y * (base + P * ev.y * inv);
    o.z = xv.z * (base + P * ev.z * inv);
    o.w = xv.w * (base + P * ev.w * inv);
    ((float4*)out)[i4] = o;
}

// ---------------- launch ----------------
extern "C" void kernel_launch(void* const* d_in, const int* in_sizes, int n_in,
                              void* d_out, int out_size) {
    const float* x     = (const float*)d_in[0];
    const float* w_qr  = (const float*)d_in[1];
    const float* b_qr  = (const float*)d_in[2];
    const float* w_vr  = (const float*)d_in[3];
    const float* b_vr  = (const float*)d_in[4];
    const float* w_up  = (const float*)d_in[5];
    const float* b_up  = (const float*)d_in[6];
    const float* ln_g  = (const float*)d_in[7];
    const float* ln_b  = (const float*)d_in[8];
    const float* w_ql  = (const float*)d_in[9];
    const float* b_ql  = (const float*)d_in[10];
    const float* w_vl  = (const float*)d_in[11];
    const float* b_vl  = (const float*)d_in[12];
    const float* w_red = (const float*)d_in[13];
    const float* bn_g  = (const float*)d_in[14];
    const float* bn_b  = (const float*)d_in[15];
    const float* bn_rm = (const float*)d_in[16];
    const float* bn_rv = (const float*)d_in[17];
    const float* w_sel = (const float*)d_in[18];
    float* out = (float*)d_out;

    k0_init<<<32, 256>>>();
    k12<<<BB*64, 256>>>(x, w_qr, b_qr, w_ql);
    k3v<<<BB, 256>>>(b_ql, w_vl, b_vl);
    k3a<<<dim3(BB, 8), 256>>>(w_vr, b_vr);
    k3b<<<dim3(BB, 16), 256>>>(w_up, b_up);
    k3c<<<BB, 256>>>(ln_g, ln_b, w_red, bn_g, bn_b, bn_rm, bn_rv, w_sel);
    k4_ctx<<<dim3(BB, 16), 512>>>(x);
    k5_final<<<(BB*CC*HWN/4)/256, 256>>>(x, out);
}

// round 6
// speedup vs baseline: 1.2100x; 1.2100x over previous
#include <cuda_runtime.h>
#include <cuda_bf16.h>

#define BB 16
#define CC 512
#define MM 256
#define HWN 4096
#define ATTN 32

// ---------------- scratch ----------------
__device__ float g_Y[BB*CC];
__device__ float g_S[BB];
__device__ float g_Gmax[BB*MM];
__device__ float g_ctx[BB*MM];
__device__ float g_up[BB*CC];
__device__ float g_v[BB*CC];
__device__ float g_c0[BB];
__device__ float g_P[BB*CC];
__device__ float g_Q[BB*CC];
__device__ float g_E[BB*HWN];
__device__ float g_Esum[BB];

__device__ __forceinline__ void atomicMaxF(float* addr, float v) {
    int old = __float_as_int(*addr);
    while (__int_as_float(old) < v) {
        int prev = atomicCAS((int*)addr, old, __float_as_int(v));
        if (prev == old) break;
        old = prev;
    }
}

__device__ __forceinline__ float blockSum256(float v, float* red) {
    int t = threadIdx.x, lane = t & 31, warp = t >> 5;
    __syncthreads();
#pragma unroll
    for (int o = 16; o; o >>= 1) v += __shfl_xor_sync(~0u, v, o);
    if (lane == 0) red[warp] = v;
    __syncthreads();
    if (warp == 0) {
        float s = (lane < 8) ? red[lane] : 0.f;
#pragma unroll
        for (int o = 4; o; o >>= 1) s += __shfl_xor_sync(~0u, s, o);
        if (lane == 0) red[0] = s;
    }
    __syncthreads();
    return red[0];
}
__device__ __forceinline__ float blockMax256(float v, float* red) {
    int t = threadIdx.x, lane = t & 31, warp = t >> 5;
    __syncthreads();
#pragma unroll
    for (int o = 16; o; o >>= 1) v = fmaxf(v, __shfl_xor_sync(~0u, v, o));
    if (lane == 0) red[warp] = v;
    __syncthreads();
    if (warp == 0) {
        float s = (lane < 8) ? red[lane] : __int_as_float(0xff800000u);
#pragma unroll
        for (int o = 4; o; o >>= 1) s = fmaxf(s, __shfl_xor_sync(~0u, s, o));
        if (lane == 0) red[0] = s;
    }
    __syncthreads();
    return red[0];
}

// ---------------- K0: init ----------------
__global__ void k0_init() {
    int i = blockIdx.x * 256 + threadIdx.x;
    if (i < BB*CC) g_Y[i] = 0.f;
    if (i < BB*MM) g_Gmax[i] = __int_as_float(0xff800000u);
    if (i < BB) { g_S[i] = 0.f; g_Esum[i] = 0.f; }
}

// ---------------- K12: block-specialized k1 (mask/Y) + k2 (tensor gmax) — R3 proven ----------------
#define K1_BLOCKS (BB*16)
__global__ __launch_bounds__(256, 2) void k12(const float* __restrict__ x,
                                              const float* __restrict__ w_qr,
                                              const float* __restrict__ b_qr,
                                              const float* __restrict__ w_ql) {
    __shared__ __align__(16) char smem_raw[2 * 128 * 40 * 2];  // 20.5KB
    int bid = blockIdx.x, t = threadIdx.x;

    if (bid < K1_BLOCKS) {
        // ===== k1 role =====
        float* sw   = (float*)smem_raw;            // [CC]
        float* se   = sw + CC;                      // [256]
        float* sred = se + 256;                     // [256]
        int b = bid >> 4, chunk = bid & 15;
        for (int i = t; i < CC; i += 256) sw[i] = w_qr[i];
        __syncthreads();

        int h = chunk * 256 + t;
        const float* xb = x + (size_t)b * CC * HWN;
        const float* xp = xb + h;
        float l0 = 0.f, l1 = 0.f, l2 = 0.f, l3 = 0.f;
#pragma unroll 4
        for (int c = 0; c < CC; c += 4) {
            l0 += sw[c]     * xp[(size_t)c * HWN];
            l1 += sw[c + 1] * xp[(size_t)(c + 1) * HWN];
            l2 += sw[c + 2] * xp[(size_t)(c + 2) * HWN];
            l3 += sw[c + 3] * xp[(size_t)(c + 3) * HWN];
        }
        float e = expf(b_qr[0] + (l0 + l1) + (l2 + l3));
        se[t] = e;
        sred[t] = e;
        __syncthreads();
        for (int s = 128; s > 0; s >>= 1) { if (t < s) sred[t] += sred[t + s]; __syncthreads(); }
        if (t == 0) atomicAdd(&g_S[b], sred[0]);

        const float4* se4 = (const float4*)se;
        for (int cc = t; cc < CC; cc += 256) {
            const float4* xr = (const float4*)(xb + (size_t)cc * HWN + chunk * 256);
            float a0 = 0.f, a1 = 0.f;
#pragma unroll 8
            for (int j = 0; j < 64; j += 2) {
                float4 xv = xr[j];     float4 ev = se4[j];
                a0 += ev.x*xv.x + ev.y*xv.y + ev.z*xv.z + ev.w*xv.w;
                float4 xw = xr[j + 1]; float4 ew = se4[j + 1];
                a1 += ew.x*xw.x + ew.y*xw.y + ew.z*xw.z + ew.w*xw.w;
            }
            atomicAdd(&g_Y[b*CC + cc], a0 + a1);
        }
    } else {
        // ===== k2 role: 128(M) x 128(N) tile, K=512, bf16 mma =====
        __nv_bfloat16 (*As)[40] = (__nv_bfloat16(*)[40])smem_raw;
        __nv_bfloat16 (*Bs)[40] = (__nv_bfloat16(*)[40])(smem_raw + 128 * 40 * 2);
        int bid2 = bid - K1_BLOCKS;
        int b = bid2 >> 6, r6 = bid2 & 63;
        int mt = r6 >> 5, nt = r6 & 31;
        int warp = t >> 5, lane = t & 31;
        int wm = warp >> 2, wn = warp & 3;          // 2 x 4 warps; warp tile 64x32
        const float* xb = x + (size_t)b * CC * HWN + nt * 128;
        const float* wq = w_ql + (size_t)mt * 128 * CC;

        float acc[4][4][4];
#pragma unroll
        for (int i = 0; i < 4; i++)
#pragma unroll
            for (int j = 0; j < 4; j++)
#pragma unroll
                for (int k = 0; k < 4; k++) acc[i][j][k] = 0.f;

        for (int k0 = 0; k0 < CC; k0 += 32) {
            __syncthreads();
#pragma unroll
            for (int p = 0; p < 16; p++) {          // A: 128x32
                int i = t + p * 256;
                int m = i >> 5, k = i & 31;
                As[m][k] = __float2bfloat16(wq[m * CC + k0 + k]);
            }
#pragma unroll
            for (int p = 0; p < 16; p++) {          // B: 32x128 -> Bs[n][k]
                int i = t + p * 256;
                int n = i & 127, k = i >> 7;
                Bs[n][k] = __float2bfloat16(xb[(size_t)(k0 + k) * HWN + n]);
            }
            __syncthreads();
#pragma unroll
            for (int kb = 0; kb < 32; kb += 16) {
                unsigned af[4][4], bf[4][2];
                int cq = kb + (lane & 3) * 2;
#pragma unroll
                for (int mf = 0; mf < 4; mf++) {
                    int r = wm * 64 + mf * 16 + (lane >> 2);
                    af[mf][0] = *(const unsigned*)&As[r][cq];
                    af[mf][1] = *(const unsigned*)&As[r + 8][cq];
                    af[mf][2] = *(const unsigned*)&As[r][cq + 8];
                    af[mf][3] = *(const unsigned*)&As[r + 8][cq + 8];
                }
#pragma unroll
                for (int nf = 0; nf < 4; nf++) {
                    int n = wn * 32 + nf * 8 + (lane >> 2);
                    bf[nf][0] = *(const unsigned*)&Bs[n][cq];
                    bf[nf][1] = *(const unsigned*)&Bs[n][cq + 8];
                }
#pragma unroll
                for (int mf = 0; mf < 4; mf++)
#pragma unroll
                    for (int nf = 0; nf < 4; nf++)
                        asm volatile(
                            "mma.sync.aligned.m16n8k16.row.col.f32.bf16.bf16.f32 "
                            "{%0,%1,%2,%3}, {%4,%5,%6,%7}, {%8,%9}, {%0,%1,%2,%3};\n"
                            : "+f"(acc[mf][nf][0]), "+f"(acc[mf][nf][1]),
                              "+f"(acc[mf][nf][2]), "+f"(acc[mf][nf][3])
                            : "r"(af[mf][0]), "r"(af[mf][1]), "r"(af[mf][2]), "r"(af[mf][3]),
                              "r"(bf[nf][0]), "r"(bf[nf][1]));
            }
        }
#pragma unroll
        for (int mf = 0; mf < 4; mf++) {
            float m0 = __int_as_float(0xff800000u), m1 = m0;
#pragma unroll
            for (int nf = 0; nf < 4; nf++) {
                m0 = fmaxf(m0, fmaxf(acc[mf][nf][0], acc[mf][nf][1]));
                m1 = fmaxf(m1, fmaxf(acc[mf][nf][2], acc[mf][nf][3]));
            }
            m0 = fmaxf(m0, __shfl_xor_sync(~0u, m0, 1));
            m0 = fmaxf(m0, __shfl_xor_sync(~0u, m0, 2));
            m1 = fmaxf(m1, __shfl_xor_sync(~0u, m1, 1));
            m1 = fmaxf(m1, __shfl_xor_sync(~0u, m1, 2));
            if ((lane & 3) == 0) {
                int r = mt * 128 + wm * 64 + mf * 16 + (lane >> 2);
                atomicMaxF(&g_Gmax[b * MM + r], m0);
                atomicMaxF(&g_Gmax[b * MM + r + 8], m1);
            }
        }
    }
}

// ---------------- K3av: blk 0..7 -> context rows; blk 8 -> softmax/v/c0.  grid (B,9) ----------------
__global__ void k3av(const float* __restrict__ w_vr, const float* __restrict__ b_vr,
                     const float* __restrict__ b_ql,
                     const float* __restrict__ w_vl, const float* __restrict__ b_vl) {
    int b = blockIdx.x, blk = blockIdx.y, t = threadIdx.x;
    int warp = t >> 5, lane = t & 31;
    if (blk < 8) {
        __shared__ float sy[CC];
        float Sinv = 1.f / g_S[b];
        for (int i = t; i < CC; i += 256) sy[i] = g_Y[b*CC + i] * Sinv;
        __syncthreads();
#pragma unroll
        for (int i = 0; i < 4; i++) {
            int r = blk * 32 + warp * 4 + i;
            const float* wr = w_vr + (size_t)r * CC;
            float a = 0.f;
#pragma unroll
            for (int c = lane; c < CC; c += 32) a += wr[c] * sy[c];
#pragma unroll
            for (int o = 16; o; o >>= 1) a += __shfl_xor_sync(~0u, a, o);
            if (lane == 0) g_ctx[b*MM + r] = a + b_vr[r];
        }
    } else {
        __shared__ float savg[MM];
        __shared__ float red[8];
        float gv = g_Gmax[b*MM + t] + b_ql[t];
        float gm = blockMax256(gv, red);
        float ge = expf(gv - gm);
        float gs = blockSum256(ge, red);
        savg[t] = ge / gs;
        float c0 = blockSum256((ge / gs) * b_vl[t], red);
        if (t == 0) g_c0[b] = c0;
        __syncthreads();
        float a0 = 0.f, a1 = 0.f;
#pragma unroll 8
        for (int m = 0; m < MM; m++) {
            float av = savg[m];
            const float* wr = w_vl + (size_t)m * CC;
            a0 += av * wr[t];
            a1 += av * wr[t + 256];
        }
        g_v[b*CC + t]       = a0;
        g_v[b*CC + t + 256] = a1;
    }
}

// ---------------- K3b: up = W_up @ ctx + b_up.  grid (B, 16) ----------------
__global__ void k3b(const float* __restrict__ w_up, const float* __restrict__ b_up) {
    __shared__ float sc[MM];
    int b = blockIdx.x, blk = blockIdx.y, t = threadIdx.x;
    int warp = t >> 5, lane = t & 31;
    if (t < MM) sc[t] = g_ctx[b*MM + t];
    __syncthreads();
#pragma unroll
    for (int i = 0; i < 4; i++) {
        int r = blk * 32 + warp * 4 + i;
        const float* wr = w_up + (size_t)r * MM;
        float a = 0.f;
#pragma unroll
        for (int m = lane; m < MM; m += 32) a += wr[m] * sc[m];
#pragma unroll
        for (int o = 16; o; o >>= 1) a += __shfl_xor_sync(~0u, a, o);
        if (lane == 0) g_up[b*CC + r] = a + b_up[r];
    }
}

// ---------------- K3c: LN + sigmoid + SK-attn -> P,Q.  grid B ----------------
__global__ void k3c(const float* __restrict__ ln_g, const float* __restrict__ ln_b,
                    const float* __restrict__ w_red, const float* __restrict__ bn_g,
                    const float* __restrict__ bn_b, const float* __restrict__ bn_rm,
                    const float* __restrict__ bn_rv, const float* __restrict__ w_sel) {
    __shared__ float sy[CC];
    __shared__ float sca[CC];
    __shared__ float ssk[ATTN];
    __shared__ float red[8];
    int b = blockIdx.x, t = threadIdx.x;
    int warp = t >> 5, lane = t & 31;

    float u0 = g_up[b*CC + t], u1 = g_up[b*CC + t + 256];
    float mean = blockSum256(u0 + u1, red) * (1.f / CC);
    float var  = blockSum256(u0*u0 + u1*u1, red) * (1.f / CC) - mean * mean;
    float rstd = rsqrtf(var + 1e-5f);
    sca[t]       = 1.f / (1.f + expf(-((u0 - mean) * rstd * ln_g[t] + ln_b[t])));
    sca[t + 256] = 1.f / (1.f + expf(-((u1 - mean) * rstd * ln_g[t + 256] + ln_b[t + 256])));

    const float invHW = 1.f / (float)HWN;
    sy[t]       = sca[t]       * (1.f + invHW) + invHW;
    sy[t + 256] = sca[t + 256] * (1.f + invHW) + invHW;
    __syncthreads();

#pragma unroll
    for (int i = 0; i < 4; i++) {
        int r = warp * 4 + i;
        const float* wr = w_red + (size_t)r * CC;
        float a = 0.f;
#pragma unroll
        for (int c = lane; c < CC; c += 32) a += wr[c] * sy[c];
#pragma unroll
        for (int o = 16; o; o >>= 1) a += __shfl_xor_sync(~0u, a, o);
        if (lane == 0) {
            a = (a - bn_rm[r]) * rsqrtf(bn_rv[r] + 1e-5f) * bn_g[r] + bn_b[r];
            ssk[r] = fmaxf(a, 0.f);
        }
    }
    __syncthreads();

#pragma unroll
    for (int i = 0; i < 2; i++) {
        int c = t + i * 256;
        float s0 = 0.f, s1 = 0.f;
        const float* w0 = w_sel + (size_t)c * ATTN;
        const float* w1 = w_sel + (size_t)(CC + c) * ATTN;
#pragma unroll
        for (int a = 0; a < ATTN; a++) { s0 += w0[a] * ssk[a]; s1 += w1[a] * ssk[a]; }
        float mx = fmaxf(s0, s1);
        float e0 = expf(s0 - mx), e1 = expf(s1 - mx);
        float inv = 1.f / (e0 + e1);
        float a0 = e0 * inv, a1 = e1 * inv;
        float ca = sca[c];
        g_P[b*CC + c] = a0 * ca + a1;
        g_Q[b*CC + c] = a1 * ca;
    }
}

// ---------------- K4: ctx per pixel = v.x + c0; exp & sum ----------------
// grid (B, 32), 512 threads: 128 pixels x 4 channel-quarters per CTA.
__global__ __launch_bounds__(512) void k4_ctx(const float* __restrict__ x) {
    __shared__ float sv[CC];
    __shared__ float part[512];
    __shared__ float red[4];
    int b = blockIdx.x, chunk = blockIdx.y, t = threadIdx.x;
    for (int i = t; i < CC; i += 512) sv[i] = g_v[b*CC + i];
    __syncthreads();
    int hp = t & 127;
    int h = chunk * 128 + hp;
    int ch0 = (t >> 7) * 128;
    const float* xp = x + (size_t)b * CC * HWN + (size_t)ch0 * HWN + h;
    float a0 = 0.f, a1 = 0.f, a2 = 0.f, a3 = 0.f;
#pragma unroll 8
    for (int c = 0; c < 128; c += 4) {
        a0 += sv[ch0 + c]     * xp[(size_t)c * HWN];
        a1 += sv[ch0 + c + 1] * xp[(size_t)(c + 1) * HWN];
        a2 += sv[ch0 + c + 2] * xp[(size_t)(c + 2) * HWN];
        a3 += sv[ch0 + c + 3] * xp[(size_t)(c + 3) * HWN];
    }
    part[t] = (a0 + a1) + (a2 + a3);
    __syncthreads();
    if (t < 128) {
        int lane = t & 31, warp = t >> 5;
        float e = expf(g_c0[b] + (part[t] + part[t + 128]) + (part[t + 256] + part[t + 384]));
        g_E[b*HWN + h] = e;
        float s = e;
#pragma unroll
        for (int o = 16; o; o >>= 1) s += __shfl_xor_sync(~0u, s, o);
        if (lane == 0) red[warp] = s;
    }
    __syncthreads();
    if (t == 0) atomicAdd(&g_Esum[b], (red[0] + red[1]) + (red[2] + red[3]));
}

// ---------------- K5: out = x * (1 + Q + P * spatial_attn) ----------------
__global__ void k5_final(const float* __restrict__ x, float* __restrict__ out) {
    int i4 = blockIdx.x * 256 + threadIdx.x;
    int h4 = i4 & 1023;
    int c  = (i4 >> 10) & 511;
    int b  = i4 >> 19;
    float4 xv = ((const float4*)x)[i4];
    float4 ev = ((const float4*)g_E)[b * (HWN/4) + h4];
    float inv = 1.f / g_Esum[b];
    float P = g_P[b*CC + c], Q = g_Q[b*CC + c];
    float base = 1.f + Q;
    float4 o;
    o.x = xv.x * (base + P * ev.x * inv);
    o.y = xv.y * (base + P * ev.y * inv);
    o.z = xv.z * (base + P * ev.z * inv);
    o.w = xv.w * (base + P * ev.w * inv);
    ((float4*)out)[i4] = o;
}

// ---------------- launch ----------------
extern "C" void kernel_launch(void* const* d_in, const int* in_sizes, int n_in,
                              void* d_out, int out_size) {
    const float* x     = (const float*)d_in[0];
    const float* w_qr  = (const float*)d_in[1];
    const float* b_qr  = (const float*)d_in[2];
    const float* w_vr  = (const float*)d_in[3];
    const float* b_vr  = (const float*)d_in[4];
    const float* w_up  = (const float*)d_in[5];
    const float* b_up  = (const float*)d_in[6];
    const float* ln_g  = (const float*)d_in[7];
    const float* ln_b  = (const float*)d_in[8];
    const float* w_ql  = (const float*)d_in[9];
    const float* b_ql  = (const float*)d_in[10];
    const float* w_vl  = (const float*)d_in[11];
    const float* b_vl  = (const float*)d_in[12];
    const float* w_red = (const float*)d_in[13];
    const float* bn_g  = (const float*)d_in[14];
    const float* bn_b  = (const float*)d_in[15];
    const float* bn_rm = (const float*)d_in[16];
    const float* bn_rv = (const float*)d_in[17];
    const float* w_sel = (const float*)d_in[18];
    float* out = (float*)d_out;

    k0_init<<<32, 256>>>();
    k12<<<K1_BLOCKS + BB*64, 256>>>(x, w_qr, b_qr, w_ql);
    k3av<<<dim3(BB, 9), 256>>>(w_vr, b_vr, b_ql, w_vl, b_vl);
    k3b<<<dim3(BB, 16), 256>>>(w_up, b_up);
    k3c<<<BB, 256>>>(ln_g, ln_b, w_red, bn_g, bn_b, bn_rm, bn_rv, w_sel);
    k4_ctx<<<dim3(BB, 32), 512>>>(x);
    k5_final<<<(BB*CC*HWN/4)/256, 256>>>(x, out);
}

// round 7
// speedup vs baseline: 1.3107x; 1.0833x over previous
#include <cuda_runtime.h>
#include <cuda_bf16.h>

#define BB 16
#define CC 512
#define MM 256
#define HWN 4096
#define ATTN 32

// ---------------- scratch ----------------
__device__ float g_Y[BB*CC];
__device__ float g_S[BB];
__device__ float g_Gmax[BB*MM];
__device__ float g_ctx[BB*MM];
__device__ float g_up[BB*CC];
__device__ float g_v[BB*CC];
__device__ float g_c0[BB];
__device__ float g_P[BB*CC];
__device__ float g_Q[BB*CC];
__device__ float g_E[BB*HWN];
__device__ float g_Esum[BB];

__device__ __forceinline__ void atomicMaxF(float* addr, float v) {
    int old = __float_as_int(*addr);
    while (__int_as_float(old) < v) {
        int prev = atomicCAS((int*)addr, old, __float_as_int(v));
        if (prev == old) break;
        old = prev;
    }
}

__device__ __forceinline__ float blockSum256(float v, float* red) {
    int t = threadIdx.x, lane = t & 31, warp = t >> 5;
    __syncthreads();
#pragma unroll
    for (int o = 16; o; o >>= 1) v += __shfl_xor_sync(~0u, v, o);
    if (lane == 0) red[warp] = v;
    __syncthreads();
    if (warp == 0) {
        float s = (lane < 8) ? red[lane] : 0.f;
#pragma unroll
        for (int o = 4; o; o >>= 1) s += __shfl_xor_sync(~0u, s, o);
        if (lane == 0) red[0] = s;
    }
    __syncthreads();
    return red[0];
}
__device__ __forceinline__ float blockMax256(float v, float* red) {
    int t = threadIdx.x, lane = t & 31, warp = t >> 5;
    __syncthreads();
#pragma unroll
    for (int o = 16; o; o >>= 1) v = fmaxf(v, __shfl_xor_sync(~0u, v, o));
    if (lane == 0) red[warp] = v;
    __syncthreads();
    if (warp == 0) {
        float s = (lane < 8) ? red[lane] : __int_as_float(0xff800000u);
#pragma unroll
        for (int o = 4; o; o >>= 1) s = fmaxf(s, __shfl_xor_sync(~0u, s, o));
        if (lane == 0) red[0] = s;
    }
    __syncthreads();
    return red[0];
}

// ---------------- K0: init ----------------
__global__ void k0_init() {
    int i = blockIdx.x * 256 + threadIdx.x;
    if (i < BB*CC) g_Y[i] = 0.f;
    if (i < BB*MM) g_Gmax[i] = __int_as_float(0xff800000u);
    if (i < BB) { g_S[i] = 0.f; g_Esum[i] = 0.f; }
}

// ---------------- K12: interleaved block-specialized k1 (mask/Y) + k2 (tensor gmax) ----
// 1536 blocks. bid%3==0 -> k1 role (512 blocks: b, 32 chunks of 128 pixels).
// else k2 role (1024 blocks: b, mt in {0,1}, nt in 0..31), 128x128 tile K=512,
// with register-staged prefetch of the B (x) slice.
#define TOTAL_BLOCKS (BB*96)
__global__ __launch_bounds__(256, 2) void k12(const float* __restrict__ x,
                                              const float* __restrict__ w_qr,
                                              const float* __restrict__ b_qr,
                                              const float* __restrict__ w_ql) {
    __shared__ __align__(16) char smem_raw[2 * 128 * 40 * 2];  // 20.5KB
    int bid = blockIdx.x, t = threadIdx.x;

    if (bid % 3 == 0) {
        // ===== k1 role: 128 pixels, 2 threads per pixel (channel halves) =====
        int k1id = bid / 3;
        int b = k1id >> 5, chunk = k1id & 31;
        float* sw    = (float*)smem_raw;         // [512]
        float* spart = sw + CC;                  // [256]
        float* se    = spart + 256;              // [128]
        for (int i = t; i < CC; i += 256) sw[i] = w_qr[i];
        __syncthreads();

        int p = t & 127, half = t >> 7;
        int h0 = chunk * 128;
        int h = h0 + p;
        int c0 = half * 256;
        const float* xb = x + (size_t)b * CC * HWN;
        const float* xp = xb + (size_t)c0 * HWN + h;
        float l0=0.f,l1=0.f,l2=0.f,l3=0.f,l4=0.f,l5=0.f,l6=0.f,l7=0.f;
#pragma unroll 4
        for (int c = 0; c < 256; c += 8) {
            l0 += sw[c0+c]   * xp[(size_t)c * HWN];
            l1 += sw[c0+c+1] * xp[(size_t)(c+1) * HWN];
            l2 += sw[c0+c+2] * xp[(size_t)(c+2) * HWN];
            l3 += sw[c0+c+3] * xp[(size_t)(c+3) * HWN];
            l4 += sw[c0+c+4] * xp[(size_t)(c+4) * HWN];
            l5 += sw[c0+c+5] * xp[(size_t)(c+5) * HWN];
            l6 += sw[c0+c+6] * xp[(size_t)(c+6) * HWN];
            l7 += sw[c0+c+7] * xp[(size_t)(c+7) * HWN];
        }
        spart[t] = ((l0+l1)+(l2+l3)) + ((l4+l5)+(l6+l7));
        __syncthreads();
        if (t < 128) {
            float e = expf(b_qr[0] + spart[t] + spart[t + 128]);
            se[t] = e;
            float s = e;
#pragma unroll
            for (int o = 16; o; o >>= 1) s += __shfl_xor_sync(~0u, s, o);
            if ((t & 31) == 0) atomicAdd(&g_S[b], s);
        }
        __syncthreads();

        // Y[c] += sum over 128 pixels; 2 rows per thread
        const float4* se4 = (const float4*)se;
#pragma unroll
        for (int i = 0; i < 2; i++) {
            int cc = t + i * 256;
            const float4* xr = (const float4*)(xb + (size_t)cc * HWN + h0);
            float a0 = 0.f, a1 = 0.f;
#pragma unroll 8
            for (int j = 0; j < 32; j += 2) {
                float4 xv = xr[j];     float4 ev = se4[j];
                a0 += ev.x*xv.x + ev.y*xv.y + ev.z*xv.z + ev.w*xv.w;
                float4 xw = xr[j + 1]; float4 ew = se4[j + 1];
                a1 += ew.x*xw.x + ew.y*xw.y + ew.z*xw.z + ew.w*xw.w;
            }
            atomicAdd(&g_Y[b*CC + cc], a0 + a1);
        }
    } else {
        // ===== k2 role =====
        __nv_bfloat16 (*As)[40] = (__nv_bfloat16(*)[40])smem_raw;
        __nv_bfloat16 (*Bs)[40] = (__nv_bfloat16(*)[40])(smem_raw + 128 * 40 * 2);
        int k2id = bid - bid / 3 - 1;
        int b = k2id >> 6, r6 = k2id & 63;
        int mt = r6 >> 5, nt = r6 & 31;
        int warp = t >> 5, lane = t & 31;
        int wm = warp >> 2, wn = warp & 3;          // 2 x 4 warps; warp tile 64x32
        const float* xb = x + (size_t)b * CC * HWN + nt * 128;
        const float* wq = w_ql + (size_t)mt * 128 * CC;

        float acc[4][4][4];
#pragma unroll
        for (int i = 0; i < 4; i++)
#pragma unroll
            for (int j = 0; j < 4; j++)
#pragma unroll
                for (int k = 0; k < 4; k++) acc[i][j][k] = 0.f;

        // prologue: stage B slice 0
        float bstage[16];
#pragma unroll
        for (int p = 0; p < 16; p++) {
            int i = t + p * 256;
            int n = i & 127, k = i >> 7;
            bstage[p] = xb[(size_t)k * HWN + n];
        }

        for (int k0 = 0; k0 < CC; k0 += 32) {
            __syncthreads();
#pragma unroll
            for (int p = 0; p < 16; p++) {          // staged B -> smem
                int i = t + p * 256;
                int n = i & 127, k = i >> 7;
                Bs[n][k] = __float2bfloat16(bstage[p]);
            }
#pragma unroll
            for (int p = 0; p < 16; p++) {          // A direct (L2-resident weights)
                int i = t + p * 256;
                int m = i >> 5, k = i & 31;
                As[m][k] = __float2bfloat16(wq[m * CC + k0 + k]);
            }
            __syncthreads();
            if (k0 + 32 < CC) {                     // prefetch next B slice
#pragma unroll
                for (int p = 0; p < 16; p++) {
                    int i = t + p * 256;
                    int n = i & 127, k = i >> 7;
                    bstage[p] = xb[(size_t)(k0 + 32 + k) * HWN + n];
                }
            }
#pragma unroll
            for (int kb = 0; kb < 32; kb += 16) {
                unsigned af[4][4], bf[4][2];
                int cq = kb + (lane & 3) * 2;
#pragma unroll
                for (int mf = 0; mf < 4; mf++) {
                    int r = wm * 64 + mf * 16 + (lane >> 2);
                    af[mf][0] = *(const unsigned*)&As[r][cq];
                    af[mf][1] = *(const unsigned*)&As[r + 8][cq];
                    af[mf][2] = *(const unsigned*)&As[r][cq + 8];
                    af[mf][3] = *(const unsigned*)&As[r + 8][cq + 8];
                }
#pragma unroll
                for (int nf = 0; nf < 4; nf++) {
                    int n = wn * 32 + nf * 8 + (lane >> 2);
                    bf[nf][0] = *(const unsigned*)&Bs[n][cq];
                    bf[nf][1] = *(const unsigned*)&Bs[n][cq + 8];
                }
#pragma unroll
                for (int mf = 0; mf < 4; mf++)
#pragma unroll
                    for (int nf = 0; nf < 4; nf++)
                        asm volatile(
                            "mma.sync.aligned.m16n8k16.row.col.f32.bf16.bf16.f32 "
                            "{%0,%1,%2,%3}, {%4,%5,%6,%7}, {%8,%9}, {%0,%1,%2,%3};\n"
                            : "+f"(acc[mf][nf][0]), "+f"(acc[mf][nf][1]),
                              "+f"(acc[mf][nf][2]), "+f"(acc[mf][nf][3])
                            : "r"(af[mf][0]), "r"(af[mf][1]), "r"(af[mf][2]), "r"(af[mf][3]),
                              "r"(bf[nf][0]), "r"(bf[nf][1]));
            }
        }
#pragma unroll
        for (int mf = 0; mf < 4; mf++) {
            float m0 = __int_as_float(0xff800000u), m1 = m0;
#pragma unroll
            for (int nf = 0; nf < 4; nf++) {
                m0 = fmaxf(m0, fmaxf(acc[mf][nf][0], acc[mf][nf][1]));
                m1 = fmaxf(m1, fmaxf(acc[mf][nf][2], acc[mf][nf][3]));
            }
            m0 = fmaxf(m0, __shfl_xor_sync(~0u, m0, 1));
            m0 = fmaxf(m0, __shfl_xor_sync(~0u, m0, 2));
            m1 = fmaxf(m1, __shfl_xor_sync(~0u, m1, 1));
            m1 = fmaxf(m1, __shfl_xor_sync(~0u, m1, 2));
            if ((lane & 3) == 0) {
                int r = mt * 128 + wm * 64 + mf * 16 + (lane >> 2);
                atomicMaxF(&g_Gmax[b * MM + r], m0);
                atomicMaxF(&g_Gmax[b * MM + r + 8], m1);
            }
        }
    }
}

// ---------------- K3av: blk 0..7 -> context rows; blk 8 -> softmax/v/c0.  grid (B,9) ----------------
__global__ void k3av(const float* __restrict__ w_vr, const float* __restrict__ b_vr,
                     const float* __restrict__ b_ql,
                     const float* __restrict__ w_vl, const float* __restrict__ b_vl) {
    int b = blockIdx.x, blk = blockIdx.y, t = threadIdx.x;
    int warp = t >> 5, lane = t & 31;
    if (blk < 8) {
        __shared__ float sy[CC];
        float Sinv = 1.f / g_S[b];
        for (int i = t; i < CC; i += 256) sy[i] = g_Y[b*CC + i] * Sinv;
        __syncthreads();
#pragma unroll
        for (int i = 0; i < 4; i++) {
            int r = blk * 32 + warp * 4 + i;
            const float* wr = w_vr + (size_t)r * CC;
            float a = 0.f;
#pragma unroll
            for (int c = lane; c < CC; c += 32) a += wr[c] * sy[c];
#pragma unroll
            for (int o = 16; o; o >>= 1) a += __shfl_xor_sync(~0u, a, o);
            if (lane == 0) g_ctx[b*MM + r] = a + b_vr[r];
        }
    } else {
        __shared__ float savg[MM];
        __shared__ float red[8];
        float gv = g_Gmax[b*MM + t] + b_ql[t];
        float gm = blockMax256(gv, red);
        float ge = expf(gv - gm);
        float gs = blockSum256(ge, red);
        savg[t] = ge / gs;
        float c0 = blockSum256((ge / gs) * b_vl[t], red);
        if (t == 0) g_c0[b] = c0;
        __syncthreads();
        float a0 = 0.f, a1 = 0.f;
#pragma unroll 8
        for (int m = 0; m < MM; m++) {
            float av = savg[m];
            const float* wr = w_vl + (size_t)m * CC;
            a0 += av * wr[t];
            a1 += av * wr[t + 256];
        }
        g_v[b*CC + t]       = a0;
        g_v[b*CC + t + 256] = a1;
    }
}

// ---------------- K3b: up = W_up @ ctx + b_up.  grid (B, 16) ----------------
__global__ void k3b(const float* __restrict__ w_up, const float* __restrict__ b_up) {
    __shared__ float sc[MM];
    int b = blockIdx.x, blk = blockIdx.y, t = threadIdx.x;
    int warp = t >> 5, lane = t & 31;
    if (t < MM) sc[t] = g_ctx[b*MM + t];
    __syncthreads();
#pragma unroll
    for (int i = 0; i < 4; i++) {
        int r = blk * 32 + warp * 4 + i;
        const float* wr = w_up + (size_t)r * MM;
        float a = 0.f;
#pragma unroll
        for (int m = lane; m < MM; m += 32) a += wr[m] * sc[m];
#pragma unroll
        for (int o = 16; o; o >>= 1) a += __shfl_xor_sync(~0u, a, o);
        if (lane == 0) g_up[b*CC + r] = a + b_up[r];
    }
}

// ---------------- K3c: LN + sigmoid + SK-attn -> P,Q.  grid B ----------------
__global__ void k3c(const float* __restrict__ ln_g, const float* __restrict__ ln_b,
                    const float* __restrict__ w_red, const float* __restrict__ bn_g,
                    const float* __restrict__ bn_b, const float* __restrict__ bn_rm,
                    const float* __restrict__ bn_rv, const float* __restrict__ w_sel) {
    __shared__ float sy[CC];
    __shared__ float sca[CC];
    __shared__ float ssk[ATTN];
    __shared__ float red[8];
    int b = blockIdx.x, t = threadIdx.x;
    int warp = t >> 5, lane = t & 31;

    float u0 = g_up[b*CC + t], u1 = g_up[b*CC + t + 256];
    float mean = blockSum256(u0 + u1, red) * (1.f / CC);
    float var  = blockSum256(u0*u0 + u1*u1, red) * (1.f / CC) - mean * mean;
    float rstd = rsqrtf(var + 1e-5f);
    sca[t]       = 1.f / (1.f + expf(-((u0 - mean) * rstd * ln_g[t] + ln_b[t])));
    sca[t + 256] = 1.f / (1.f + expf(-((u1 - mean) * rstd * ln_g[t + 256] + ln_b[t + 256])));

    const float invHW = 1.f / (float)HWN;
    sy[t]       = sca[t]       * (1.f + invHW) + invHW;
    sy[t + 256] = sca[t + 256] * (1.f + invHW) + invHW;
    __syncthreads();

#pragma unroll
    for (int i = 0; i < 4; i++) {
        int r = warp * 4 + i;
        const float* wr = w_red + (size_t)r * CC;
        float a = 0.f;
#pragma unroll
        for (int c = lane; c < CC; c += 32) a += wr[c] * sy[c];
#pragma unroll
        for (int o = 16; o; o >>= 1) a += __shfl_xor_sync(~0u, a, o);
        if (lane == 0) {
            a = (a - bn_rm[r]) * rsqrtf(bn_rv[r] + 1e-5f) * bn_g[r] + bn_b[r];
            ssk[r] = fmaxf(a, 0.f);
        }
    }
    __syncthreads();

#pragma unroll
    for (int i = 0; i < 2; i++) {
        int c = t + i * 256;
        float s0 = 0.f, s1 = 0.f;
        const float* w0 = w_sel + (size_t)c * ATTN;
        const float* w1 = w_sel + (size_t)(CC + c) * ATTN;
#pragma unroll
        for (int a = 0; a < ATTN; a++) { s0 += w0[a] * ssk[a]; s1 += w1[a] * ssk[a]; }
        float mx = fmaxf(s0, s1);
        float e0 = expf(s0 - mx), e1 = expf(s1 - mx);
        float inv = 1.f / (e0 + e1);
        float a0 = e0 * inv, a1 = e1 * inv;
        float ca = sca[c];
        g_P[b*CC + c] = a0 * ca + a1;
        g_Q[b*CC + c] = a1 * ca;
    }
}

// ---------------- K4: ctx per pixel = v.x + c0; exp & sum ----------------
// grid (B, 32), 512 threads: 128 pixels x 4 channel-quarters per CTA.
__global__ __launch_bounds__(512) void k4_ctx(const float* __restrict__ x) {
    __shared__ float sv[CC];
    __shared__ float part[512];
    __shared__ float red[4];
    int b = blockIdx.x, chunk = blockIdx.y, t = threadIdx.x;
    for (int i = t; i < CC; i += 512) sv[i] = g_v[b*CC + i];
    __syncthreads();
    int hp = t & 127;
    int h = chunk * 128 + hp;
    int ch0 = (t >> 7) * 128;
    const float* xp = x + (size_t)b * CC * HWN + (size_t)ch0 * HWN + h;
    float a0 = 0.f, a1 = 0.f, a2 = 0.f, a3 = 0.f;
#pragma unroll 8
    for (int c = 0; c < 128; c += 4) {
        a0 += sv[ch0 + c]     * xp[(size_t)c * HWN];
        a1 += sv[ch0 + c + 1] * xp[(size_t)(c + 1) * HWN];
        a2 += sv[ch0 + c + 2] * xp[(size_t)(c + 2) * HWN];
        a3 += sv[ch0 + c + 3] * xp[(size_t)(c + 3) * HWN];
    }
    part[t] = (a0 + a1) + (a2 + a3);
    __syncthreads();
    if (t < 128) {
        int lane = t & 31, warp = t >> 5;
        float e = expf(g_c0[b] + (part[t] + part[t + 128]) + (part[t + 256] + part[t + 384]));
        g_E[b*HWN + h] = e;
        float s = e;
#pragma unroll
        for (int o = 16; o; o >>= 1) s += __shfl_xor_sync(~0u, s, o);
        if (lane == 0) red[warp] = s;
    }
    __syncthreads();
    if (t == 0) atomicAdd(&g_Esum[b], (red[0] + red[1]) + (red[2] + red[3]));
}

// ---------------- K5: out = x * (1 + Q + P * spatial_attn) ----------------
__global__ void k5_final(const float* __restrict__ x, float* __restrict__ out) {
    int i4 = blockIdx.x * 256 + threadIdx.x;
    int h4 = i4 & 1023;
    int c  = (i4 >> 10) & 511;
    int b  = i4 >> 19;
    float4 xv = ((const float4*)x)[i4];
    float4 ev = ((const float4*)g_E)[b * (HWN/4) + h4];
    float inv = 1.f / g_Esum[b];
    float P = g_P[b*CC + c], Q = g_Q[b*CC + c];
    float base = 1.f + Q;
    float4 o;
    o.x = xv.x * (base + P * ev.x * inv);
    o.y = xv.y * (base + P * ev.y * inv);
    o.z = xv.z * (base + P * ev.z * inv);
    o.w = xv.w * (base + P * ev.w * inv);
    ((float4*)out)[i4] = o;
}

// ---------------- launch ----------------
extern "C" void kernel_launch(void* const* d_in, const int* in_sizes, int n_in,
                              void* d_out, int out_size) {
    const float* x     = (const float*)d_in[0];
    const float* w_qr  = (const float*)d_in[1];
    const float* b_qr  = (const float*)d_in[2];
    const float* w_vr  = (const float*)d_in[3];
    const float* b_vr  = (const float*)d_in[4];
    const float* w_up  = (const float*)d_in[5];
    const float* b_up  = (const float*)d_in[6];
    const float* ln_g  = (const float*)d_in[7];
    const float* ln_b  = (const float*)d_in[8];
    const float* w_ql  = (const float*)d_in[9];
    const float* b_ql  = (const float*)d_in[10];
    const float* w_vl  = (const float*)d_in[11];
    const float* b_vl  = (const float*)d_in[12];
    const float* w_red = (const float*)d_in[13];
    const float* bn_g  = (const float*)d_in[14];
    const float* bn_b  = (const float*)d_in[15];
    const float* bn_rm = (const float*)d_in[16];
    const float* bn_rv = (const float*)d_in[17];
    const float* w_sel = (const float*)d_in[18];
    float* out = (float*)d_out;

    k0_init<<<32, 256>>>();
    k12<<<TOTAL_BLOCKS, 256>>>(x, w_qr, b_qr, w_ql);
    k3av<<<dim3(BB, 9), 256>>>(w_vr, b_vr, b_ql, w_vl, b_vl);
    k3b<<<dim3(BB, 16), 256>>>(w_up, b_up);
    k3c<<<BB, 256>>>(ln_g, ln_b, w_red, bn_g, bn_b, bn_rm, bn_rv, w_sel);
    k4_ctx<<<dim3(BB, 32), 512>>>(x);
    k5_final<<<(BB*CC*HWN/4)/256, 256>>>(x, out);
}

// round 8
// speedup vs baseline: 1.3124x; 1.0013x over previous
#include <cuda_runtime.h>
#include <cuda_bf16.h>

#define BB 16
#define CC 512
#define MM 256
#define HWN 4096
#define ATTN 32

// ---------------- scratch ----------------
__device__ float g_Y[BB*CC];
__device__ float g_S[BB];
__device__ float g_Gmax[BB*MM];
__device__ float g_ctx[BB*MM];
__device__ float g_up[BB*CC];
__device__ float g_v[BB*CC];
__device__ float g_c0[BB];
__device__ float g_P[BB*CC];
__device__ float g_Q[BB*CC];
__device__ float g_Esum[BB];
__device__ int   g_cnt[BB];

__device__ __forceinline__ void atomicMaxF(float* addr, float v) {
    int old = __float_as_int(*addr);
    while (__int_as_float(old) < v) {
        int prev = atomicCAS((int*)addr, old, __float_as_int(v));
        if (prev == old) break;
        old = prev;
    }
}

__device__ __forceinline__ float blockSum256(float v, float* red) {
    int t = threadIdx.x, lane = t & 31, warp = t >> 5;
    __syncthreads();
#pragma unroll
    for (int o = 16; o; o >>= 1) v += __shfl_xor_sync(~0u, v, o);
    if (lane == 0) red[warp] = v;
    __syncthreads();
    if (warp == 0) {
        float s = (lane < 8) ? red[lane] : 0.f;
#pragma unroll
        for (int o = 4; o; o >>= 1) s += __shfl_xor_sync(~0u, s, o);
        if (lane == 0) red[0] = s;
    }
    __syncthreads();
    return red[0];
}
__device__ __forceinline__ float blockMax256(float v, float* red) {
    int t = threadIdx.x, lane = t & 31, warp = t >> 5;
    __syncthreads();
#pragma unroll
    for (int o = 16; o; o >>= 1) v = fmaxf(v, __shfl_xor_sync(~0u, v, o));
    if (lane == 0) red[warp] = v;
    __syncthreads();
    if (warp == 0) {
        float s = (lane < 8) ? red[lane] : __int_as_float(0xff800000u);
#pragma unroll
        for (int o = 4; o; o >>= 1) s = fmaxf(s, __shfl_xor_sync(~0u, s, o));
        if (lane == 0) red[0] = s;
    }
    __syncthreads();
    return red[0];
}

// ---------------- K0: init ----------------
__global__ void k0_init() {
    int i = blockIdx.x * 256 + threadIdx.x;
    if (i < BB*CC) g_Y[i] = 0.f;
    if (i < BB*MM) g_Gmax[i] = __int_as_float(0xff800000u);
    if (i < BB) { g_S[i] = 0.f; g_Esum[i] = 0.f; g_cnt[i] = 0; }
}

// ---------------- K12: interleaved k1 (mask/Y) + k2 (M=256 tensor gmax), 512 threads ----
// 1024 blocks, parity split. odd -> k1 (512: b x 32 chunks of 128 px).
// even -> k2 (512: b x 32 nt), tile 256(M) x 128(N), K=512, B prefetch staged.
__global__ __launch_bounds__(512) void k12(const float* __restrict__ x,
                                           const float* __restrict__ w_qr,
                                           const float* __restrict__ b_qr,
                                           const float* __restrict__ w_ql) {
    __shared__ __align__(16) char smem_raw[256*40*2 + 128*40*2];  // 30.0KB
    int bid = blockIdx.x, t = threadIdx.x;
    int id = bid >> 1;

    if (bid & 1) {
        // ===== k1 role: 128 pixels, 4 threads per pixel (128 channels each) =====
        int b = id >> 5, chunk = id & 31;
        float* sw    = (float*)smem_raw;      // [512]
        float* spart = sw + CC;               // [512]
        float* se    = spart + 512;           // [128]
        for (int i = t; i < CC; i += 512) sw[i] = w_qr[i];
        __syncthreads();

        int p = t & 127, q = t >> 7;
        int c0 = q * 128;
        int h0 = chunk * 128;
        int h = h0 + p;
        const float* xb = x + (size_t)b * CC * HWN;
        const float* xp = xb + (size_t)c0 * HWN + h;
        float l0=0.f,l1=0.f,l2=0.f,l3=0.f,l4=0.f,l5=0.f,l6=0.f,l7=0.f;
#pragma unroll 4
        for (int c = 0; c < 128; c += 8) {
            l0 += sw[c0+c]   * xp[(size_t)c * HWN];
            l1 += sw[c0+c+1] * xp[(size_t)(c+1) * HWN];
            l2 += sw[c0+c+2] * xp[(size_t)(c+2) * HWN];
            l3 += sw[c0+c+3] * xp[(size_t)(c+3) * HWN];
            l4 += sw[c0+c+4] * xp[(size_t)(c+4) * HWN];
            l5 += sw[c0+c+5] * xp[(size_t)(c+5) * HWN];
            l6 += sw[c0+c+6] * xp[(size_t)(c+6) * HWN];
            l7 += sw[c0+c+7] * xp[(size_t)(c+7) * HWN];
        }
        spart[t] = ((l0+l1)+(l2+l3)) + ((l4+l5)+(l6+l7));
        __syncthreads();
        if (t < 128) {
            float e = expf(b_qr[0] + (spart[t] + spart[t+128]) + (spart[t+256] + spart[t+384]));
            se[t] = e;
            float s = e;
#pragma unroll
            for (int o = 16; o; o >>= 1) s += __shfl_xor_sync(~0u, s, o);
            if ((t & 31) == 0) atomicAdd(&g_S[b], s);
        }
        __syncthreads();

        // Y[c] += sum over 128 pixels; one row per thread
        const float4* se4 = (const float4*)se;
        const float4* xr = (const float4*)(xb + (size_t)t * HWN + h0);
        float a0 = 0.f, a1 = 0.f;
#pragma unroll 8
        for (int j = 0; j < 32; j += 2) {
            float4 xv = xr[j];     float4 ev = se4[j];
            a0 += ev.x*xv.x + ev.y*xv.y + ev.z*xv.z + ev.w*xv.w;
            float4 xw = xr[j + 1]; float4 ew = se4[j + 1];
            a1 += ew.x*xw.x + ew.y*xw.y + ew.z*xw.z + ew.w*xw.w;
        }
        atomicAdd(&g_Y[b*CC + t], a0 + a1);
    } else {
        // ===== k2 role: 256(M) x 128(N), K=512, 16 warps 4x4, warp tile 64x32 =====
        __nv_bfloat16 (*As)[40] = (__nv_bfloat16(*)[40])smem_raw;
        __nv_bfloat16 (*Bs)[40] = (__nv_bfloat16(*)[40])(smem_raw + 256 * 40 * 2);
        int b = id >> 5, nt = id & 31;
        int warp = t >> 5, lane = t & 31;
        int wm = warp >> 2, wn = warp & 3;
        const float* xb = x + (size_t)b * CC * HWN + nt * 128;

        float acc[4][4][4];
#pragma unroll
        for (int i = 0; i < 4; i++)
#pragma unroll
            for (int j = 0; j < 4; j++)
#pragma unroll
                for (int k = 0; k < 4; k++) acc[i][j][k] = 0.f;

        float bstage[8];
#pragma unroll
        for (int p = 0; p < 8; p++) {
            int i = t + p * 512;
            int n = i & 127, k = i >> 7;
            bstage[p] = xb[(size_t)k * HWN + n];
        }

        for (int k0 = 0; k0 < CC; k0 += 32) {
            __syncthreads();
#pragma unroll
            for (int p = 0; p < 8; p++) {           // staged B -> smem
                int i = t + p * 512;
                int n = i & 127, k = i >> 7;
                Bs[n][k] = __float2bfloat16(bstage[p]);
            }
#pragma unroll
            for (int p = 0; p < 16; p++) {          // A: 256x32 direct (L2-resident)
                int i = t + p * 512;
                int m = i >> 5, k = i & 31;
                As[m][k] = __float2bfloat16(w_ql[m * CC + k0 + k]);
            }
            __syncthreads();
            if (k0 + 32 < CC) {
#pragma unroll
                for (int p = 0; p < 8; p++) {
                    int i = t + p * 512;
                    int n = i & 127, k = i >> 7;
                    bstage[p] = xb[(size_t)(k0 + 32 + k) * HWN + n];
                }
            }
#pragma unroll
            for (int kb = 0; kb < 32; kb += 16) {
                unsigned af[4][4], bf[4][2];
                int cq = kb + (lane & 3) * 2;
#pragma unroll
                for (int mf = 0; mf < 4; mf++) {
                    int r = wm * 64 + mf * 16 + (lane >> 2);
                    af[mf][0] = *(const unsigned*)&As[r][cq];
                    af[mf][1] = *(const unsigned*)&As[r + 8][cq];
                    af[mf][2] = *(const unsigned*)&As[r][cq + 8];
                    af[mf][3] = *(const unsigned*)&As[r + 8][cq + 8];
                }
#pragma unroll
                for (int nf = 0; nf < 4; nf++) {
                    int n = wn * 32 + nf * 8 + (lane >> 2);
                    bf[nf][0] = *(const unsigned*)&Bs[n][cq];
                    bf[nf][1] = *(const unsigned*)&Bs[n][cq + 8];
                }
#pragma unroll
                for (int mf = 0; mf < 4; mf++)
#pragma unroll
                    for (int nf = 0; nf < 4; nf++)
                        asm volatile(
                            "mma.sync.aligned.m16n8k16.row.col.f32.bf16.bf16.f32 "
                            "{%0,%1,%2,%3}, {%4,%5,%6,%7}, {%8,%9}, {%0,%1,%2,%3};\n"
                            : "+f"(acc[mf][nf][0]), "+f"(acc[mf][nf][1]),
                              "+f"(acc[mf][nf][2]), "+f"(acc[mf][nf][3])
                            : "r"(af[mf][0]), "r"(af[mf][1]), "r"(af[mf][2]), "r"(af[mf][3]),
                              "r"(bf[nf][0]), "r"(bf[nf][1]));
            }
        }
#pragma unroll
        for (int mf = 0; mf < 4; mf++) {
            float m0 = __int_as_float(0xff800000u), m1 = m0;
#pragma unroll
            for (int nf = 0; nf < 4; nf++) {
                m0 = fmaxf(m0, fmaxf(acc[mf][nf][0], acc[mf][nf][1]));
                m1 = fmaxf(m1, fmaxf(acc[mf][nf][2], acc[mf][nf][3]));
            }
            m0 = fmaxf(m0, __shfl_xor_sync(~0u, m0, 1));
            m0 = fmaxf(m0, __shfl_xor_sync(~0u, m0, 2));
            m1 = fmaxf(m1, __shfl_xor_sync(~0u, m1, 1));
            m1 = fmaxf(m1, __shfl_xor_sync(~0u, m1, 2));
            if ((lane & 3) == 0) {
                int r = wm * 64 + mf * 16 + (lane >> 2);
                atomicMaxF(&g_Gmax[b * MM + r], m0);
                atomicMaxF(&g_Gmax[b * MM + r + 8], m1);
            }
        }
    }
}

// ---------------- K3av: blk 0..7 -> context rows; blk 8 -> softmax/v/c0.  grid (B,9) ----------------
__global__ void k3av(const float* __restrict__ w_vr, const float* __restrict__ b_vr,
                     const float* __restrict__ b_ql,
                     const float* __restrict__ w_vl, const float* __restrict__ b_vl) {
    int b = blockIdx.x, blk = blockIdx.y, t = threadIdx.x;
    int warp = t >> 5, lane = t & 31;
    if (blk < 8) {
        __shared__ float sy[CC];
        float Sinv = 1.f / g_S[b];
        for (int i = t; i < CC; i += 256) sy[i] = g_Y[b*CC + i] * Sinv;
        __syncthreads();
#pragma unroll
        for (int i = 0; i < 4; i++) {
            int r = blk * 32 + warp * 4 + i;
            const float* wr = w_vr + (size_t)r * CC;
            float a = 0.f;
#pragma unroll
            for (int c = lane; c < CC; c += 32) a += wr[c] * sy[c];
#pragma unroll
            for (int o = 16; o; o >>= 1) a += __shfl_xor_sync(~0u, a, o);
            if (lane == 0) g_ctx[b*MM + r] = a + b_vr[r];
        }
    } else {
        __shared__ float savg[MM];
        __shared__ float red[8];
        float gv = g_Gmax[b*MM + t] + b_ql[t];
        float gm = blockMax256(gv, red);
        float ge = expf(gv - gm);
        float gs = blockSum256(ge, red);
        savg[t] = ge / gs;
        float c0 = blockSum256((ge / gs) * b_vl[t], red);
        if (t == 0) g_c0[b] = c0;
        __syncthreads();
        float a0 = 0.f, a1 = 0.f;
#pragma unroll 8
        for (int m = 0; m < MM; m++) {
            float av = savg[m];
            const float* wr = w_vl + (size_t)m * CC;
            a0 += av * wr[t];
            a1 += av * wr[t + 256];
        }
        g_v[b*CC + t]       = a0;
        g_v[b*CC + t + 256] = a1;
    }
}

// ---------------- K3b: up = W_up @ ctx + b_up.  grid (B, 16) ----------------
__global__ void k3b(const float* __restrict__ w_up, const float* __restrict__ b_up) {
    __shared__ float sc[MM];
    int b = blockIdx.x, blk = blockIdx.y, t = threadIdx.x;
    int warp = t >> 5, lane = t & 31;
    if (t < MM) sc[t] = g_ctx[b*MM + t];
    __syncthreads();
#pragma unroll
    for (int i = 0; i < 4; i++) {
        int r = blk * 32 + warp * 4 + i;
        const float* wr = w_up + (size_t)r * MM;
        float a = 0.f;
#pragma unroll
        for (int m = lane; m < MM; m += 32) a += wr[m] * sc[m];
#pragma unroll
        for (int o = 16; o; o >>= 1) a += __shfl_xor_sync(~0u, a, o);
        if (lane == 0) g_up[b*CC + r] = a + b_up[r];
    }
}

// ---------------- K3c: LN + sigmoid + SK-attn -> P,Q.  grid B ----------------
__global__ void k3c(const float* __restrict__ ln_g, const float* __restrict__ ln_b,
                    const float* __restrict__ w_red, const float* __restrict__ bn_g,
                    const float* __restrict__ bn_b, const float* __restrict__ bn_rm,
                    const float* __restrict__ bn_rv, const float* __restrict__ w_sel) {
    __shared__ float sy[CC];
    __shared__ float sca[CC];
    __shared__ float ssk[ATTN];
    __shared__ float red[8];
    int b = blockIdx.x, t = threadIdx.x;
    int warp = t >> 5, lane = t & 31;

    float u0 = g_up[b*CC + t], u1 = g_up[b*CC + t + 256];
    float mean = blockSum256(u0 + u1, red) * (1.f / CC);
    float var  = blockSum256(u0*u0 + u1*u1, red) * (1.f / CC) - mean * mean;
    float rstd = rsqrtf(var + 1e-5f);
    sca[t]       = 1.f / (1.f + expf(-((u0 - mean) * rstd * ln_g[t] + ln_b[t])));
    sca[t + 256] = 1.f / (1.f + expf(-((u1 - mean) * rstd * ln_g[t + 256] + ln_b[t + 256])));

    const float invHW = 1.f / (float)HWN;
    sy[t]       = sca[t]       * (1.f + invHW) + invHW;
    sy[t + 256] = sca[t + 256] * (1.f + invHW) + invHW;
    __syncthreads();

#pragma unroll
    for (int i = 0; i < 4; i++) {
        int r = warp * 4 + i;
        const float* wr = w_red + (size_t)r * CC;
        float a = 0.f;
#pragma unroll
        for (int c = lane; c < CC; c += 32) a += wr[c] * sy[c];
#pragma unroll
        for (int o = 16; o; o >>= 1) a += __shfl_xor_sync(~0u, a, o);
        if (lane == 0) {
            a = (a - bn_rm[r]) * rsqrtf(bn_rv[r] + 1e-5f) * bn_g[r] + bn_b[r];
            ssk[r] = fmaxf(a, 0.f);
        }
    }
    __syncthreads();

#pragma unroll
    for (int i = 0; i < 2; i++) {
        int c = t + i * 256;
        float s0 = 0.f, s1 = 0.f;
        const float* w0 = w_sel + (size_t)c * ATTN;
        const float* w1 = w_sel + (size_t)(CC + c) * ATTN;
#pragma unroll
        for (int a = 0; a < ATTN; a++) { s0 += w0[a] * ssk[a]; s1 += w1[a] * ssk[a]; }
        float mx = fmaxf(s0, s1);
        float e0 = expf(s0 - mx), e1 = expf(s1 - mx);
        float inv = 1.f / (e0 + e1);
        float a0 = e0 * inv, a1 = e1 * inv;
        float ca = sca[c];
        g_P[b*CC + c] = a0 * ca + a1;
        g_Q[b*CC + c] = a1 * ca;
    }
}

// ---------------- K45: fused ctx+exp+Esum (per-batch spin barrier) + final output ----
// grid (B, 32), 256 threads. Each CTA: 128 pixels. All 512 CTAs co-resident
// (256 thr, ~48 regs -> >=5 CTAs/SM capacity), so the per-batch barrier is safe.
__global__ __launch_bounds__(256) void k45(const float* __restrict__ x,
                                           float* __restrict__ out) {
    __shared__ float sv[CC];
    __shared__ float sP[CC];
    __shared__ float sQ[CC];
    __shared__ float spart[256];
    __shared__ float se[128];
    __shared__ float red[4];
    __shared__ float sEinv;
    int b = blockIdx.x, chunk = blockIdx.y, t = threadIdx.x;
    for (int i = t; i < CC; i += 256) {
        sv[i] = g_v[b*CC + i];
        sP[i] = g_P[b*CC + i];
        sQ[i] = g_Q[b*CC + i];
    }
    __syncthreads();

    int p = t & 127, half = t >> 7;
    int c0 = half * 256;
    int h0 = chunk * 128;
    const float* xb = x + (size_t)b * CC * HWN;
    const float* xp = xb + (size_t)c0 * HWN + h0 + p;
    float a0 = 0.f, a1 = 0.f, a2 = 0.f, a3 = 0.f;
#pragma unroll 8
    for (int c = 0; c < 256; c += 4) {
        a0 += sv[c0 + c]     * xp[(size_t)c * HWN];
        a1 += sv[c0 + c + 1] * xp[(size_t)(c + 1) * HWN];
        a2 += sv[c0 + c + 2] * xp[(size_t)(c + 2) * HWN];
        a3 += sv[c0 + c + 3] * xp[(size_t)(c + 3) * HWN];
    }
    spart[t] = (a0 + a1) + (a2 + a3);
    __syncthreads();
    if (t < 128) {
        float e = expf(g_c0[b] + spart[t] + spart[t + 128]);
        se[t] = e;
        float s = e;
#pragma unroll
        for (int o = 16; o; o >>= 1) s += __shfl_xor_sync(~0u, s, o);
        if ((t & 31) == 0) red[t >> 5] = s;
    }
    __syncthreads();
    if (t == 0) {
        atomicAdd(&g_Esum[b], (red[0] + red[1]) + (red[2] + red[3]));
        __threadfence();
        atomicAdd(&g_cnt[b], 1);
        // spin until all 32 CTAs of this batch have contributed
        volatile int* vc = (volatile int*)&g_cnt[b];
        while (*vc < 32) { }
        __threadfence();
        sEinv = 1.f / *((volatile float*)&g_Esum[b]);
    }
    __syncthreads();
    float inv = sEinv;

    // final: out = x * (1 + Q + P * e * inv); x chunk is L2-hot from phase 1
    const float4* se4 = (const float4*)se;
    const float4* x4 = (const float4*)(xb + h0);
    float4* o4 = (float4*)(out + (size_t)b * CC * HWN + h0);
    // row stride in float4 units across full HWN:
    for (int i = t; i < CC * 32; i += 256) {
        int row = i >> 5, f4 = i & 31;
        float4 xv = x4[(size_t)row * (HWN/4) + f4];
        float4 ev = se4[f4];
        float P = sP[row], base = 1.f + sQ[row];
        float4 o;
        o.x = xv.x * (base + P * ev.x * inv);
        o.y = xv.y * (base + P * ev.y * inv);
        o.z = xv.z * (base + P * ev.z * inv);
        o.w = xv.w * (base + P * ev.w * inv);
        o4[(size_t)row * (HWN/4) + f4] = o;
    }
}

// ---------------- launch ----------------
extern "C" void kernel_launch(void* const* d_in, const int* in_sizes, int n_in,
                              void* d_out, int out_size) {
    const float* x     = (const float*)d_in[0];
    const float* w_qr  = (const float*)d_in[1];
    const float* b_qr  = (const float*)d_in[2];
    const float* w_vr  = (const float*)d_in[3];
    const float* b_vr  = (const float*)d_in[4];
    const float* w_up  = (const float*)d_in[5];
    const float* b_up  = (const float*)d_in[6];
    const float* ln_g  = (const float*)d_in[7];
    const float* ln_b  = (const float*)d_in[8];
    const float* w_ql  = (const float*)d_in[9];
    const float* b_ql  = (const float*)d_in[10];
    const float* w_vl  = (const float*)d_in[11];
    const float* b_vl  = (const float*)d_in[12];
    const float* w_red = (const float*)d_in[13];
    const float* bn_g  = (const float*)d_in[14];
    const float* bn_b  = (const float*)d_in[15];
    const float* bn_rm = (const float*)d_in[16];
    const float* bn_rv = (const float*)d_in[17];
    const float* w_sel = (const float*)d_in[18];
    float* out = (float*)d_out;

    k0_init<<<32, 256>>>();
    k12<<<BB*64, 512>>>(x, w_qr, b_qr, w_ql);
    k3av<<<dim3(BB, 9), 256>>>(w_vr, b_vr, b_ql, w_vl, b_vl);
    k3b<<<dim3(BB, 16), 256>>>(w_up, b_up);
    k3c<<<BB, 256>>>(ln_g, ln_b, w_red, bn_g, bn_b, bn_rm, bn_rv, w_sel);
    k45<<<dim3(BB, 32), 256>>>(x, out);
}